// round 15
// baseline (speedup 1.0000x reference)
#include <cuda_runtime.h>
#include <math.h>
#include <stdint.h>

// ---------------- problem constants ----------------
#define CB   32
#define CN   4096
#define CD   256
#define CH   4
#define CHD  64
#define CS   16
#define CGH  128
#define CMH  1024
#define CT   (CB*CN)      // 131072 tokens
#define CBS  (CB*CS)      // 512 slot rows
#define CV8  (CT*8)       // 1048576 grid-enc vectors

// ---------------- scratch (device globals) ----------------
__device__ float g_x    [CT*CD];        // LN'd features
__device__ float g_kv   [CT*512];       // final k|v
__device__ float g_wkv  [CD*512];       // [Wk|Wv]
__device__ float g_slots[CBS*CD];
__device__ float g_sn   [CBS*CD];       // LN'd slots
__device__ float g_q    [CBS*CD];
__device__ float g_attn [(size_t)CB*CH*CN*CS]; // [b,h,kk,16]
__device__ float g_rowsum[CB*CH*CS];
__device__ float g_upd  [CBS*CD];
__device__ float g_upd2 [CBS*CD];
__device__ float g_gi   [CBS*3*CD];
__device__ float g_gh   [CBS*3*CD];
__device__ float g_mlp1 [CBS*CMH];

// ---------------- tf32 MMA helpers ----------------
__device__ __forceinline__ uint32_t f2tf(float f) {
    uint32_t u;
    asm("cvt.rna.tf32.f32 %0, %1;" : "=r"(u) : "f"(f));
    return u;
}
__device__ __forceinline__ void mma_tf32(float* d, const uint32_t* a, const uint32_t* b) {
    asm volatile(
        "mma.sync.aligned.m16n8k8.row.col.f32.tf32.tf32.f32 "
        "{%0,%1,%2,%3}, {%4,%5,%6,%7}, {%8,%9}, {%0,%1,%2,%3};\n"
        : "+f"(d[0]), "+f"(d[1]), "+f"(d[2]), "+f"(d[3])
        : "r"(a[0]), "r"(a[1]), "r"(a[2]), "r"(a[3]), "r"(b[0]), "r"(b[1]));
}

// ---------------- small utility kernels ----------------
__global__ void k_copy(const float* __restrict__ src, float* __restrict__ dst, int n) {
    int i = blockIdx.x * 256 + threadIdx.x;
    if (i < n) dst[i] = src[i];
}
__global__ void k_zero(float* __restrict__ p, int n) {
    int i = blockIdx.x * 256 + threadIdx.x;
    if (i < n) p[i] = 0.f;
}
__global__ void k_build_wkv(const float* __restrict__ Wk, const float* __restrict__ Wv,
                            float* __restrict__ Wkv) {
    int i = blockIdx.x * 256 + threadIdx.x;   // < 256*512
    int d = i >> 9, j = i & 511;
    Wkv[i] = (j < 256) ? Wk[d * 256 + j] : Wv[d * 256 + (j - 256)];
}

// LayerNorm over 256 features; one block per row; generic input row stride.
__global__ __launch_bounds__(256) void k_ln256(
    const float* __restrict__ in, int instride,
    const float* __restrict__ s, const float* __restrict__ bb,
    float* __restrict__ out)
{
    int t = blockIdx.x;
    int i = threadIdx.x;
    float v = in[(size_t)t * instride + i];
    float sum = v, sq = v * v;
    #pragma unroll
    for (int o = 16; o > 0; o >>= 1) {
        sum += __shfl_xor_sync(~0u, sum, o);
        sq  += __shfl_xor_sync(~0u, sq, o);
    }
    __shared__ float ssum[8], ssq[8];
    int w = i >> 5, l = i & 31;
    if (l == 0) { ssum[w] = sum; ssq[w] = sq; }
    __syncthreads();
    if (w == 0) {
        float a  = (l < 8) ? ssum[l] : 0.f;
        float b2 = (l < 8) ? ssq[l] : 0.f;
        #pragma unroll
        for (int o = 4; o > 0; o >>= 1) {
            a  += __shfl_xor_sync(~0u, a, o);
            b2 += __shfl_xor_sync(~0u, b2, o);
        }
        if (l == 0) { ssum[0] = a; ssq[0] = b2; }
    }
    __syncthreads();
    float m   = ssum[0] * (1.f / 256.f);
    float var = ssq[0] * (1.f / 256.f) - m * m;
    float rs  = rsqrtf(var + 1e-6f);
    out[(size_t)t * 256 + i] = (v - m) * rs * s[i] + bb[i];
}

// ============================================================================
// k_fused: for a 128-token x 128-col tile of x@Wkv:
//   stage1: tf32 MMA  acc = x(128x256) @ Wkv(:,col0:col0+128)
//   epilogue: + positional, LN64 per head-vector -> smem IN (256 vecs x 64, tf32)
//   stage2 (x2 halves of 128 vecs): hidden = relu(IN@W1+b1) (smem only),
//           out = hidden@W2 + b2 -> g_kv.   W1/W2 smem-resident.
// Dynamic smem (uint32 units):
//   IN  [0,     17408) : 256 x 68
//   W1s [17408, 25856) : 64 x 132
//   W2s [25856, 34560) : 128 x 68
//   HS  [34560, 51456) : 128 x 132   (stage1 As/Bs alias this region)
// ============================================================================
#define FUSED_SMEM_U32 51456
#define FUSED_SMEM_BYTES (FUSED_SMEM_U32 * 4)
__global__ __launch_bounds__(256) void k_fused(
    const float* __restrict__ A, const float* __restrict__ Bm,
    const float* __restrict__ gridsrc, const float* __restrict__ Wp,
    const float* __restrict__ ges, const float* __restrict__ geb,
    const float* __restrict__ W1, const float* __restrict__ b1,
    const float* __restrict__ W2, const float* __restrict__ b2,
    float* __restrict__ out)
{
    extern __shared__ uint32_t sm[];
    uint32_t* IN  = sm;            // 256 x 68
    uint32_t* W1s = sm + 17408;    // 64 x 132
    uint32_t* W2s = sm + 25856;    // 128 x 68
    uint32_t* HS  = sm + 34560;    // 128 x 132
    uint32_t* As  = sm + 34560;    // alias: 128 x 36 (stage1)
    uint32_t* Bs  = sm + 39168;    // alias: 32 x 132 (stage1)

    int tid = threadIdx.x;
    int lane = tid & 31;
    int g = lane >> 2, t = lane & 3;
    int wid = tid >> 5;
    int wm = wid & 3, wn = wid >> 2;
    int cb = blockIdx.x;                 // column block (0..3)
    int row0 = blockIdx.y * 128;         // token base
    int col0 = cb * 128;

    // ---- stage W1 (64x128) and W2 (128x64) as tf32 ----
    #pragma unroll
    for (int it = 0; it < 8; it++) {
        int f4 = tid + it * 256;
        int k = f4 >> 5, n4 = (f4 & 31) * 4;
        float4 v = *reinterpret_cast<const float4*>(W1 + (size_t)k * 128 + n4);
        *reinterpret_cast<uint4*>(&W1s[k * 132 + n4]) =
            make_uint4(f2tf(v.x), f2tf(v.y), f2tf(v.z), f2tf(v.w));
    }
    #pragma unroll
    for (int it = 0; it < 8; it++) {
        int f4 = tid + it * 256;
        int k = f4 >> 4, n4 = (f4 & 15) * 4;
        float4 v = *reinterpret_cast<const float4*>(W2 + (size_t)k * 64 + n4);
        *reinterpret_cast<uint4*>(&W2s[k * 68 + n4]) =
            make_uint4(f2tf(v.x), f2tf(v.y), f2tf(v.z), f2tf(v.w));
    }

    // ---- stage 1: acc = A(128x256) @ Wkv(256, col0:+128) ----
    float acc[2][8][4];
    #pragma unroll
    for (int mt = 0; mt < 2; mt++)
        #pragma unroll
        for (int nt = 0; nt < 8; nt++)
            #pragma unroll
            for (int c = 0; c < 4; c++) acc[mt][nt][c] = 0.f;

    for (int kt = 0; kt < 256; kt += 32) {
        #pragma unroll
        for (int it = 0; it < 4; it++) {
            int f4 = tid + it * 256;
            int m = f4 >> 3, k4 = (f4 & 7) * 4;
            float4 v = *reinterpret_cast<const float4*>(A + (size_t)(row0 + m) * 256 + kt + k4);
            *reinterpret_cast<uint4*>(&As[m * 36 + k4]) =
                make_uint4(f2tf(v.x), f2tf(v.y), f2tf(v.z), f2tf(v.w));
        }
        #pragma unroll
        for (int it = 0; it < 4; it++) {
            int f4 = tid + it * 256;
            int k = f4 >> 5, n4 = (f4 & 31) * 4;
            float4 v = *reinterpret_cast<const float4*>(Bm + (size_t)(kt + k) * 512 + col0 + n4);
            *reinterpret_cast<uint4*>(&Bs[k * 132 + n4]) =
                make_uint4(f2tf(v.x), f2tf(v.y), f2tf(v.z), f2tf(v.w));
        }
        __syncthreads();
        #pragma unroll
        for (int k8 = 0; k8 < 4; k8++) {
            int k0 = k8 * 8;
            uint32_t a[2][4], b[8][2];
            #pragma unroll
            for (int mt = 0; mt < 2; mt++) {
                int m = wm * 32 + mt * 16;
                a[mt][0] = As[(m + g) * 36 + k0 + t];
                a[mt][1] = As[(m + 8 + g) * 36 + k0 + t];
                a[mt][2] = As[(m + g) * 36 + k0 + t + 4];
                a[mt][3] = As[(m + 8 + g) * 36 + k0 + t + 4];
            }
            #pragma unroll
            for (int nt = 0; nt < 8; nt++) {
                int n = wn * 64 + nt * 8 + g;
                b[nt][0] = Bs[(k0 + t) * 132 + n];
                b[nt][1] = Bs[(k0 + t + 4) * 132 + n];
            }
            #pragma unroll
            for (int mt = 0; mt < 2; mt++)
                #pragma unroll
                for (int nt = 0; nt < 8; nt++)
                    mma_tf32(acc[mt][nt], a[mt], b[nt]);
        }
        __syncthreads();
    }

    // ---- stage-1 epilogue: positional add + LN64 -> IN (tf32) ----
    #pragma unroll
    for (int mt = 0; mt < 2; mt++) {
        int lr0 = wm * 32 + mt * 16 + g;     // local token row
        int lr1 = lr0 + 8;
        int r0 = row0 + lr0, r1 = row0 + lr1;
        float p0a = gridsrc[(size_t)r0 * 258 + 256], p1a = gridsrc[(size_t)r0 * 258 + 257];
        float p0b = gridsrc[(size_t)r1 * 258 + 256], p1b = gridsrc[(size_t)r1 * 258 + 257];
        float s0 = 0.f, q0 = 0.f, s1 = 0.f, q1 = 0.f;
        #pragma unroll
        for (int nt = 0; nt < 8; nt++) {
            int col = col0 + wn * 64 + nt * 8 + t * 2;   // global col for Wp
            int jm = col & 255;
            float w00 = Wp[jm],       w01 = Wp[jm + 1];
            float w10 = Wp[256 + jm], w11 = Wp[257 + jm];
            float* c = acc[mt][nt];
            c[0] += p0a * w00 + p1a * w10;
            c[1] += p0a * w01 + p1a * w11;
            c[2] += p0b * w00 + p1b * w10;
            c[3] += p0b * w01 + p1b * w11;
            s0 += c[0] + c[1]; q0 += c[0] * c[0] + c[1] * c[1];
            s1 += c[2] + c[3]; q1 += c[2] * c[2] + c[3] * c[3];
        }
        #pragma unroll
        for (int o = 1; o <= 2; o <<= 1) {
            s0 += __shfl_xor_sync(~0u, s0, o);
            q0 += __shfl_xor_sync(~0u, q0, o);
            s1 += __shfl_xor_sync(~0u, s1, o);
            q1 += __shfl_xor_sync(~0u, q1, o);
        }
        float m0 = s0 * (1.f / 64.f), m1 = s1 * (1.f / 64.f);
        float rs0 = rsqrtf(q0 * (1.f / 64.f) - m0 * m0 + 1e-6f);
        float rs1 = rsqrtf(q1 * (1.f / 64.f) - m1 * m1 + 1e-6f);
        #pragma unroll
        for (int nt = 0; nt < 8; nt++) {
            int e = nt * 8 + t * 2;              // 0..63 within head-vector
            float sc0 = ges[e], sc1 = ges[e + 1];
            float bb0 = geb[e], bb1 = geb[e + 1];
            float* c = acc[mt][nt];
            // vector index = local_token*2 + wn
            uint32_t* p0 = &IN[(lr0 * 2 + wn) * 68 + e];
            uint32_t* p1 = &IN[(lr1 * 2 + wn) * 68 + e];
            p0[0] = f2tf((c[0] - m0) * rs0 * sc0 + bb0);
            p0[1] = f2tf((c[1] - m0) * rs0 * sc1 + bb1);
            p1[0] = f2tf((c[2] - m1) * rs1 * sc0 + bb0);
            p1[1] = f2tf((c[3] - m1) * rs1 * sc1 + bb1);
        }
    }
    __syncthreads();   // IN complete; As/Bs dead (HS may now be written)

    // ---- stage 2: grid-enc MLP on 256 vectors, two halves of 128 ----
    #pragma unroll
    for (int mh = 0; mh < 2; mh++) {
        // GEMM1: (128x64) @ W1(64x128), warp tile 32x64
        float acc1[2][8][4];
        #pragma unroll
        for (int mt = 0; mt < 2; mt++)
            #pragma unroll
            for (int nt = 0; nt < 8; nt++)
                #pragma unroll
                for (int c = 0; c < 4; c++) acc1[mt][nt][c] = 0.f;
        #pragma unroll
        for (int k8 = 0; k8 < 8; k8++) {
            int k0 = k8 * 8;
            uint32_t a[2][4], b[8][2];
            #pragma unroll
            for (int mt = 0; mt < 2; mt++) {
                int m = mh * 128 + wm * 32 + mt * 16;
                a[mt][0] = IN[(m + g) * 68 + k0 + t];
                a[mt][1] = IN[(m + 8 + g) * 68 + k0 + t];
                a[mt][2] = IN[(m + g) * 68 + k0 + t + 4];
                a[mt][3] = IN[(m + 8 + g) * 68 + k0 + t + 4];
            }
            #pragma unroll
            for (int nt = 0; nt < 8; nt++) {
                int n = wn * 64 + nt * 8 + g;
                b[nt][0] = W1s[(k0 + t) * 132 + n];
                b[nt][1] = W1s[(k0 + t + 4) * 132 + n];
            }
            #pragma unroll
            for (int mt = 0; mt < 2; mt++)
                #pragma unroll
                for (int nt = 0; nt < 8; nt++)
                    mma_tf32(acc1[mt][nt], a[mt], b[nt]);
        }
        // bias + relu -> HS
        #pragma unroll
        for (int mt = 0; mt < 2; mt++) {
            int r0 = wm * 32 + mt * 16 + g;
            int r1 = r0 + 8;
            #pragma unroll
            for (int nt = 0; nt < 8; nt++) {
                int col = wn * 64 + nt * 8 + t * 2;
                float bb0 = b1[col], bb1 = b1[col + 1];
                float* c = acc1[mt][nt];
                HS[r0 * 132 + col]     = f2tf(fmaxf(c[0] + bb0, 0.f));
                HS[r0 * 132 + col + 1] = f2tf(fmaxf(c[1] + bb1, 0.f));
                HS[r1 * 132 + col]     = f2tf(fmaxf(c[2] + bb0, 0.f));
                HS[r1 * 132 + col + 1] = f2tf(fmaxf(c[3] + bb1, 0.f));
            }
        }
        __syncthreads();

        // GEMM2: (128x128) @ W2(128x64), warp tile 32x32
        float acc2[2][4][4];
        #pragma unroll
        for (int mt = 0; mt < 2; mt++)
            #pragma unroll
            for (int nt = 0; nt < 4; nt++)
                #pragma unroll
                for (int c = 0; c < 4; c++) acc2[mt][nt][c] = 0.f;
        #pragma unroll
        for (int k8 = 0; k8 < 16; k8++) {
            int k0 = k8 * 8;
            uint32_t a[2][4], b[4][2];
            #pragma unroll
            for (int mt = 0; mt < 2; mt++) {
                int m = wm * 32 + mt * 16;
                a[mt][0] = HS[(m + g) * 132 + k0 + t];
                a[mt][1] = HS[(m + 8 + g) * 132 + k0 + t];
                a[mt][2] = HS[(m + g) * 132 + k0 + t + 4];
                a[mt][3] = HS[(m + 8 + g) * 132 + k0 + t + 4];
            }
            #pragma unroll
            for (int nt = 0; nt < 4; nt++) {
                int n = wn * 32 + nt * 8 + g;
                b[nt][0] = W2s[(k0 + t) * 68 + n];
                b[nt][1] = W2s[(k0 + t + 4) * 68 + n];
            }
            #pragma unroll
            for (int mt = 0; mt < 2; mt++)
                #pragma unroll
                for (int nt = 0; nt < 4; nt++)
                    mma_tf32(acc2[mt][nt], a[mt], b[nt]);
        }
        // epilogue: + b2, store to kv
        #pragma unroll
        for (int mt = 0; mt < 2; mt++) {
            int v0 = mh * 128 + wm * 32 + mt * 16 + g;   // local vector index
            int v1 = v0 + 8;
            int tok0 = row0 + (v0 >> 1), hv0 = v0 & 1;
            int tok1 = row0 + (v1 >> 1), hv1 = v1 & 1;
            #pragma unroll
            for (int nt = 0; nt < 4; nt++) {
                int e = wn * 32 + nt * 8 + t * 2;
                float bb0 = b2[e], bb1 = b2[e + 1];
                float* c = acc2[mt][nt];
                *reinterpret_cast<float2*>(out + (size_t)tok0 * 512 + col0 + hv0 * 64 + e) =
                    make_float2(c[0] + bb0, c[1] + bb1);
                *reinterpret_cast<float2*>(out + (size_t)tok1 * 512 + col0 + hv1 * 64 + e) =
                    make_float2(c[2] + bb0, c[3] + bb1);
            }
        }
        __syncthreads();   // HS reads done before next half overwrites
    }
}

// ---------------- small SGEMM: BM=32 BN=64 BK=32, 256 thr, 2x4 microtile
// EPI: 0 plain, 1 +bias, 2 +bias+relu, 3 *scale, 4 res + acc + bias
template<int EPI>
__global__ __launch_bounds__(256) void k_small(
    const float* __restrict__ A, const float* __restrict__ Bm, float* __restrict__ C,
    int M, int Nc, int K,
    const float* __restrict__ bias, const float* __restrict__ res, float scale)
{
    const int BM = 32, BN = 64, BK = 32;
    __shared__ float As[BK][BM + 4];
    __shared__ float Bs[BK][BN];
    int tid = threadIdx.x;
    int tx = tid & 15, ty = tid >> 4;
    int row0 = blockIdx.y * BM;
    int col0 = blockIdx.x * BN;

    float acc[2][4];
    #pragma unroll
    for (int i = 0; i < 2; i++)
        #pragma unroll
        for (int j = 0; j < 4; j++) acc[i][j] = 0.f;

    for (int k0 = 0; k0 < K; k0 += BK) {
        {
            int r = tid >> 3, c = (tid & 7) * 4;
            float4 v = *reinterpret_cast<const float4*>(A + (size_t)(row0 + r) * K + k0 + c);
            As[c + 0][r] = v.x; As[c + 1][r] = v.y;
            As[c + 2][r] = v.z; As[c + 3][r] = v.w;
        }
        #pragma unroll
        for (int it = 0; it < 2; ++it) {
            int f = tid + it * 256;
            int br = f >> 4, bc = (f & 15) * 4;
            *reinterpret_cast<float4*>(&Bs[br][bc]) =
                *reinterpret_cast<const float4*>(Bm + (size_t)(k0 + br) * Nc + col0 + bc);
        }
        __syncthreads();
        #pragma unroll
        for (int k = 0; k < BK; k++) {
            float4 b4 = *reinterpret_cast<const float4*>(&Bs[k][tx * 4]);
            float a0 = As[k][ty];
            float a1 = As[k][ty + 16];
            acc[0][0] = fmaf(a0, b4.x, acc[0][0]);
            acc[0][1] = fmaf(a0, b4.y, acc[0][1]);
            acc[0][2] = fmaf(a0, b4.z, acc[0][2]);
            acc[0][3] = fmaf(a0, b4.w, acc[0][3]);
            acc[1][0] = fmaf(a1, b4.x, acc[1][0]);
            acc[1][1] = fmaf(a1, b4.y, acc[1][1]);
            acc[1][2] = fmaf(a1, b4.z, acc[1][2]);
            acc[1][3] = fmaf(a1, b4.w, acc[1][3]);
        }
        __syncthreads();
    }

    int n = col0 + tx * 4;
    #pragma unroll
    for (int i = 0; i < 2; i++) {
        int m = row0 + ty + i * 16;
        float4 r;
        r.x = acc[i][0]; r.y = acc[i][1]; r.z = acc[i][2]; r.w = acc[i][3];
        if (EPI == 1) {
            float4 bv = *reinterpret_cast<const float4*>(bias + n);
            r.x += bv.x; r.y += bv.y; r.z += bv.z; r.w += bv.w;
        } else if (EPI == 2) {
            float4 bv = *reinterpret_cast<const float4*>(bias + n);
            r.x = fmaxf(r.x + bv.x, 0.f); r.y = fmaxf(r.y + bv.y, 0.f);
            r.z = fmaxf(r.z + bv.z, 0.f); r.w = fmaxf(r.w + bv.w, 0.f);
        } else if (EPI == 3) {
            r.x *= scale; r.y *= scale; r.z *= scale; r.w *= scale;
        } else if (EPI == 4) {
            float4 bv = *reinterpret_cast<const float4*>(bias + n);
            float4 rv = *reinterpret_cast<const float4*>(res + (size_t)m * Nc + n);
            r.x += bv.x + rv.x; r.y += bv.y + rv.y;
            r.z += bv.z + rv.z; r.w += bv.w + rv.w;
        }
        *reinterpret_cast<float4*>(C + (size_t)m * Nc + n) = r;
    }
}

// ---------------- attention pass 1: logits + softmax over slots + rowsum
__global__ __launch_bounds__(256) void k_attn1(
    const float* __restrict__ q,
    const float* __restrict__ kv,
    float* __restrict__ attn,
    float* __restrict__ rowsum)
{
    int bh = blockIdx.y;
    int b = bh >> 2, h = bh & 3;
    int kk = blockIdx.x * 256 + threadIdx.x;
    int tid = threadIdx.x;

    __shared__ float qs[16][64];
    __shared__ float rs[16];
    {
        int row = tid >> 4, col = (tid & 15) * 4;
        float4 v = *reinterpret_cast<const float4*>(
            q + (size_t)(b * 16 + row) * 256 + h * 64 + col);
        *reinterpret_cast<float4*>(&qs[row][col]) = v;
        if (tid < 16) rs[tid] = 0.f;
    }
    __syncthreads();

    const float* kp = kv + (size_t)(b * 4096 + kk) * 512 + h * 64;
    float acc[16];
    #pragma unroll
    for (int s = 0; s < 16; s++) acc[s] = 0.f;
    #pragma unroll
    for (int ec = 0; ec < 16; ec++) {
        float4 k4 = *reinterpret_cast<const float4*>(kp + ec * 4);
        #pragma unroll
        for (int s = 0; s < 16; s++) {
            float4 q4 = *reinterpret_cast<const float4*>(&qs[s][ec * 4]);
            acc[s] = fmaf(k4.x, q4.x, acc[s]);
            acc[s] = fmaf(k4.y, q4.y, acc[s]);
            acc[s] = fmaf(k4.z, q4.z, acc[s]);
            acc[s] = fmaf(k4.w, q4.w, acc[s]);
        }
    }
    float mx = acc[0];
    #pragma unroll
    for (int s = 1; s < 16; s++) mx = fmaxf(mx, acc[s]);
    float tot = 0.f;
    #pragma unroll
    for (int s = 0; s < 16; s++) { acc[s] = expf(acc[s] - mx); tot += acc[s]; }
    float inv = 1.f / tot;
    float* ap = attn + ((size_t)bh * 4096 + kk) * 16;
    #pragma unroll
    for (int s4 = 0; s4 < 4; s4++) {
        float4 o;
        o.x = acc[s4 * 4 + 0] * inv;
        o.y = acc[s4 * 4 + 1] * inv;
        o.z = acc[s4 * 4 + 2] * inv;
        o.w = acc[s4 * 4 + 3] * inv;
        *reinterpret_cast<float4*>(ap + s4 * 4) = o;
        atomicAdd(&rs[s4 * 4 + 0], o.x);
        atomicAdd(&rs[s4 * 4 + 1], o.y);
        atomicAdd(&rs[s4 * 4 + 2], o.z);
        atomicAdd(&rs[s4 * 4 + 3], o.w);
    }
    __syncthreads();
    if (tid < 16) atomicAdd(&rowsum[bh * 16 + tid], rs[tid]);
}

// ---------------- attention pass 2: upd = (attn / (rowsum+eps)) @ v
__global__ __launch_bounds__(256) void k_attn2(
    const float* __restrict__ attn,
    const float* __restrict__ rowsum,
    const float* __restrict__ kv,
    float* __restrict__ upd)
{
    int bh = blockIdx.y;
    int b = bh >> 2, h = bh & 3;
    int seg = blockIdx.x;
    int tid = threadIdx.x;
    int e = tid & 63, kg = tid >> 6;

    __shared__ float inv[16];
    __shared__ float red[4][16][64];
    if (tid < 16) inv[tid] = 1.f / (rowsum[bh * 16 + tid] + 1e-8f);
    __syncthreads();

    float acc[16];
    #pragma unroll
    for (int s = 0; s < 16; s++) acc[s] = 0.f;

    const float* abase = attn + (size_t)bh * 4096 * 16;
    #pragma unroll 4
    for (int j = 0; j < 128; j++) {
        int kk = seg * 512 + kg + j * 4;
        const float* ap = abase + (size_t)kk * 16;
        float vv = kv[(size_t)(b * 4096 + kk) * 512 + 256 + h * 64 + e];
        float4 a0 = *reinterpret_cast<const float4*>(ap + 0);
        float4 a1 = *reinterpret_cast<const float4*>(ap + 4);
        float4 a2 = *reinterpret_cast<const float4*>(ap + 8);
        float4 a3 = *reinterpret_cast<const float4*>(ap + 12);
        acc[0]  = fmaf(a0.x, vv, acc[0]);  acc[1]  = fmaf(a0.y, vv, acc[1]);
        acc[2]  = fmaf(a0.z, vv, acc[2]);  acc[3]  = fmaf(a0.w, vv, acc[3]);
        acc[4]  = fmaf(a1.x, vv, acc[4]);  acc[5]  = fmaf(a1.y, vv, acc[5]);
        acc[6]  = fmaf(a1.z, vv, acc[6]);  acc[7]  = fmaf(a1.w, vv, acc[7]);
        acc[8]  = fmaf(a2.x, vv, acc[8]);  acc[9]  = fmaf(a2.y, vv, acc[9]);
        acc[10] = fmaf(a2.z, vv, acc[10]); acc[11] = fmaf(a2.w, vv, acc[11]);
        acc[12] = fmaf(a3.x, vv, acc[12]); acc[13] = fmaf(a3.y, vv, acc[13]);
        acc[14] = fmaf(a3.z, vv, acc[14]); acc[15] = fmaf(a3.w, vv, acc[15]);
    }
    #pragma unroll
    for (int s = 0; s < 16; s++) red[kg][s][e] = acc[s];
    __syncthreads();
    if (kg == 0) {
        #pragma unroll
        for (int s = 0; s < 16; s++) {
            float t = red[0][s][e] + red[1][s][e] + red[2][s][e] + red[3][s][e];
            atomicAdd(&upd[(size_t)(b * 16 + s) * 256 + h * 64 + e], t * inv[s]);
        }
    }
}

// ---------------- GRU update (elementwise), one block per slot row
__global__ __launch_bounds__(256) void k_gru(
    const float* __restrict__ gi, const float* __restrict__ gh,
    const float* __restrict__ bhn, float* __restrict__ slots)
{
    int r = blockIdx.x, d = threadIdx.x;
    size_t gb = (size_t)r * 768 + d;
    float ir = gi[gb], iz = gi[gb + 256], inn = gi[gb + 512];
    float hr = gh[gb], hz = gh[gb + 256], hn  = gh[gb + 512];
    float rr = 1.f / (1.f + expf(-(ir + hr)));
    float zz = 1.f / (1.f + expf(-(iz + hz)));
    float nn = tanhf(inn + rr * (hn + bhn[d]));
    size_t sb = (size_t)r * 256 + d;
    slots[sb] = (1.f - zz) * nn + zz * slots[sb];
}

// ---------------- host orchestration ----------------
extern "C" void kernel_launch(void* const* d_in, const int* in_sizes, int n_in,
                              void* d_out, int out_size)
{
    (void)in_sizes; (void)n_in;
    const float* slots_in = (const float*)d_in[0];
    const float* inputs   = (const float*)d_in[1];
    const float* ln_in_s  = (const float*)d_in[2];
    const float* ln_in_b  = (const float*)d_in[3];
    const float* Wk       = (const float*)d_in[4];
    const float* Wv       = (const float*)d_in[5];
    const float* Wp       = (const float*)d_in[6];
    const float* ge_ln_s  = (const float*)d_in[7];
    const float* ge_ln_b  = (const float*)d_in[8];
    const float* ge_W1    = (const float*)d_in[9];
    const float* ge_b1    = (const float*)d_in[10];
    const float* ge_W2    = (const float*)d_in[11];
    const float* ge_b2    = (const float*)d_in[12];
    const float* lnq_s    = (const float*)d_in[13];
    const float* lnq_b    = (const float*)d_in[14];
    const float* Wq       = (const float*)d_in[15];
    const float* Wo       = (const float*)d_in[16];
    const float* gru_Wi   = (const float*)d_in[17];
    const float* gru_bi   = (const float*)d_in[18];
    const float* gru_Wh   = (const float*)d_in[19];
    const float* gru_bhn  = (const float*)d_in[20];
    const float* mlp_ln_s = (const float*)d_in[21];
    const float* mlp_ln_b = (const float*)d_in[22];
    const float* mlp_W1   = (const float*)d_in[23];
    const float* mlp_b1   = (const float*)d_in[24];
    const float* mlp_W2   = (const float*)d_in[25];
    const float* mlp_b2   = (const float*)d_in[26];

    float *x, *kvb, *wkv, *slots, *sn, *q, *attn, *rowsum;
    float *upd, *upd2, *gi, *gh, *mlp1;
    cudaGetSymbolAddress((void**)&x,      g_x);
    cudaGetSymbolAddress((void**)&kvb,    g_kv);
    cudaGetSymbolAddress((void**)&wkv,    g_wkv);
    cudaGetSymbolAddress((void**)&slots,  g_slots);
    cudaGetSymbolAddress((void**)&sn,     g_sn);
    cudaGetSymbolAddress((void**)&q,      g_q);
    cudaGetSymbolAddress((void**)&attn,   g_attn);
    cudaGetSymbolAddress((void**)&rowsum, g_rowsum);
    cudaGetSymbolAddress((void**)&upd,    g_upd);
    cudaGetSymbolAddress((void**)&upd2,   g_upd2);
    cudaGetSymbolAddress((void**)&gi,     g_gi);
    cudaGetSymbolAddress((void**)&gh,     g_gh);
    cudaGetSymbolAddress((void**)&mlp1,   g_mlp1);

    cudaFuncSetAttribute(k_fused, cudaFuncAttributeMaxDynamicSharedMemorySize,
                         FUSED_SMEM_BYTES);

    // ---- setup ----
    k_copy<<<(CBS*CD + 255) / 256, 256>>>(slots_in, slots, CBS*CD);
    k_build_wkv<<<(CD*512 + 255) / 256, 256>>>(Wk, Wv, wkv);
    k_ln256<<<CT, 256>>>(inputs, 258, ln_in_s, ln_in_b, x);

    // kv = grid_enc( LN64( x@[Wk|Wv] + pos ) )  — fully fused, one kernel
    k_fused<<<dim3(4, 1024), 256, FUSED_SMEM_BYTES>>>(
        x, wkv, inputs, Wp, ge_ln_s, ge_ln_b,
        ge_W1, ge_b1, ge_W2, ge_b2, kvb);

    // ---- iterations ----
    for (int it = 0; it < 3; it++) {
        k_zero<<<(CB*CH*CS + 255) / 256, 256>>>(rowsum, CB*CH*CS);
        k_zero<<<(CBS*CD + 255) / 256, 256>>>(upd, CBS*CD);

        k_ln256<<<CBS, 256>>>(slots, 256, lnq_s, lnq_b, sn);
        k_small<3><<<dim3(256/64, CBS/32), 256>>>(sn, Wq, q, CBS, 256, 256,
                                                  nullptr, nullptr, 0.125f);
        k_attn1<<<dim3(16, CB*CH), 256>>>(q, kvb, attn, rowsum);
        k_attn2<<<dim3(8, CB*CH), 256>>>(attn, rowsum, kvb, upd);

        k_small<0><<<dim3(256/64, CBS/32), 256>>>(upd, Wo, upd2, CBS, 256, 256,
                                                  nullptr, nullptr, 1.f);
        k_small<1><<<dim3(768/64, CBS/32), 256>>>(upd2, gru_Wi, gi, CBS, 768, 256,
                                                  gru_bi, nullptr, 1.f);
        k_small<0><<<dim3(768/64, CBS/32), 256>>>(slots, gru_Wh, gh, CBS, 768, 256,
                                                  nullptr, nullptr, 1.f);
        k_gru<<<CBS, 256>>>(gi, gh, gru_bhn, slots);

        k_ln256<<<CBS, 256>>>(slots, 256, mlp_ln_s, mlp_ln_b, sn);
        k_small<2><<<dim3(1024/64, CBS/32), 256>>>(sn, mlp_W1, mlp1, CBS, 1024, 256,
                                                   mlp_b1, nullptr, 1.f);
        k_small<4><<<dim3(256/64, CBS/32), 256>>>(mlp1, mlp_W2, slots, CBS, 256, 1024,
                                                  mlp_b2, slots, 1.f);
    }

    k_copy<<<(CBS*CD + 255) / 256, 256>>>(slots, (float*)d_out, CBS*CD);
    (void)out_size;
}

// round 16
// speedup vs baseline: 1.2531x; 1.2531x over previous
#include <cuda_runtime.h>
#include <math.h>
#include <stdint.h>

// ---------------- problem constants ----------------
#define CB   32
#define CN   4096
#define CD   256
#define CH   4
#define CHD  64
#define CS   16
#define CGH  128
#define CMH  1024
#define CT   (CB*CN)      // 131072 tokens
#define CBS  (CB*CS)      // 512 slot rows
#define CV8  (CT*8)       // 1048576 grid-enc vectors

// ---------------- scratch (device globals) ----------------
__device__ float g_x    [CT*CD];        // LN'd features
__device__ float g_pre  [CT*512];       // LN'd kpre|vpre (viewed as CV8 x 64)
__device__ float g_kv   [CT*512];       // final k|v
__device__ float g_wkv  [CD*512];       // [Wk|Wv]
__device__ float g_wog  [CD*768];       // Wo @ gru_Wi  (folded)
__device__ float g_slots[CBS*CD];
__device__ float g_sn   [CBS*CD];       // LN'd slots
__device__ float g_q    [CBS*CD];
__device__ float g_attn [(size_t)CB*CH*CN*CS]; // [b,h,kk,16]
__device__ float g_upd  [CBS*CD];
__device__ float g_gi   [CBS*3*CD];
__device__ float g_gh   [CBS*3*CD];
__device__ float g_mlp1 [CBS*CMH];

// ---------------- tf32 MMA helpers ----------------
__device__ __forceinline__ uint32_t f2tf(float f) {
    uint32_t u;
    asm("cvt.rna.tf32.f32 %0, %1;" : "=r"(u) : "f"(f));
    return u;
}
__device__ __forceinline__ void mma_tf32(float* d, const uint32_t* a, const uint32_t* b) {
    asm volatile(
        "mma.sync.aligned.m16n8k8.row.col.f32.tf32.tf32.f32 "
        "{%0,%1,%2,%3}, {%4,%5,%6,%7}, {%8,%9}, {%0,%1,%2,%3};\n"
        : "+f"(d[0]), "+f"(d[1]), "+f"(d[2]), "+f"(d[3])
        : "r"(a[0]), "r"(a[1]), "r"(a[2]), "r"(a[3]), "r"(b[0]), "r"(b[1]));
}

// ---------------- small utility kernels ----------------
__global__ void k_copy(const float* __restrict__ src, float* __restrict__ dst, int n) {
    int i = blockIdx.x * 256 + threadIdx.x;
    if (i < n) dst[i] = src[i];
}
__global__ void k_build_wkv(const float* __restrict__ Wk, const float* __restrict__ Wv,
                            float* __restrict__ Wkv) {
    int i = blockIdx.x * 256 + threadIdx.x;   // < 256*512
    int d = i >> 9, j = i & 511;
    Wkv[i] = (j < 256) ? Wk[d * 256 + j] : Wv[d * 256 + (j - 256)];
}

// LayerNorm over 256 features; one block per row; generic input row stride.
__global__ __launch_bounds__(256) void k_ln256(
    const float* __restrict__ in, int instride,
    const float* __restrict__ s, const float* __restrict__ bb,
    float* __restrict__ out)
{
    int t = blockIdx.x;
    int i = threadIdx.x;
    float v = in[(size_t)t * instride + i];
    float sum = v, sq = v * v;
    #pragma unroll
    for (int o = 16; o > 0; o >>= 1) {
        sum += __shfl_xor_sync(~0u, sum, o);
        sq  += __shfl_xor_sync(~0u, sq, o);
    }
    __shared__ float ssum[8], ssq[8];
    int w = i >> 5, l = i & 31;
    if (l == 0) { ssum[w] = sum; ssq[w] = sq; }
    __syncthreads();
    if (w == 0) {
        float a  = (l < 8) ? ssum[l] : 0.f;
        float b2 = (l < 8) ? ssq[l] : 0.f;
        #pragma unroll
        for (int o = 4; o > 0; o >>= 1) {
            a  += __shfl_xor_sync(~0u, a, o);
            b2 += __shfl_xor_sync(~0u, b2, o);
        }
        if (l == 0) { ssum[0] = a; ssq[0] = b2; }
    }
    __syncthreads();
    float m   = ssum[0] * (1.f / 256.f);
    float var = ssq[0] * (1.f / 256.f) - m * m;
    float rs  = rsqrtf(var + 1e-6f);
    out[(size_t)t * 256 + i] = (v - m) * rs * s[i] + bb[i];
}

// ============================================================================
// k_kvpre: pre = LN64( x(131072x256) @ Wkv(256x512) + positional )
// tf32 MMA, block tile 128x128, 8 warps (warp tile 32x64), BK=32.
// ============================================================================
__global__ __launch_bounds__(256) void k_kvpre(
    const float* __restrict__ A, const float* __restrict__ Bm, float* __restrict__ C,
    const float* __restrict__ gridsrc, const float* __restrict__ Wp,
    const float* __restrict__ ges, const float* __restrict__ geb)
{
    __shared__ uint32_t As[128 * 36];
    __shared__ uint32_t Bs[32 * 132];
    int tid = threadIdx.x;
    int lane = tid & 31;
    int g = lane >> 2, t = lane & 3;
    int wid = tid >> 5;
    int wm = wid & 3, wn = wid >> 2;
    int row0 = blockIdx.y * 128, col0 = blockIdx.x * 128;

    float acc[2][8][4];
    #pragma unroll
    for (int mt = 0; mt < 2; mt++)
        #pragma unroll
        for (int nt = 0; nt < 8; nt++)
            #pragma unroll
            for (int c = 0; c < 4; c++) acc[mt][nt][c] = 0.f;

    for (int kt = 0; kt < 256; kt += 32) {
        #pragma unroll
        for (int it = 0; it < 4; it++) {
            int f4 = tid + it * 256;
            int m = f4 >> 3, k4 = (f4 & 7) * 4;
            float4 v = *reinterpret_cast<const float4*>(A + (size_t)(row0 + m) * 256 + kt + k4);
            *reinterpret_cast<uint4*>(&As[m * 36 + k4]) =
                make_uint4(f2tf(v.x), f2tf(v.y), f2tf(v.z), f2tf(v.w));
        }
        #pragma unroll
        for (int it = 0; it < 4; it++) {
            int f4 = tid + it * 256;
            int k = f4 >> 5, n4 = (f4 & 31) * 4;
            float4 v = *reinterpret_cast<const float4*>(Bm + (size_t)(kt + k) * 512 + col0 + n4);
            *reinterpret_cast<uint4*>(&Bs[k * 132 + n4]) =
                make_uint4(f2tf(v.x), f2tf(v.y), f2tf(v.z), f2tf(v.w));
        }
        __syncthreads();
        #pragma unroll
        for (int k8 = 0; k8 < 4; k8++) {
            int k0 = k8 * 8;
            uint32_t a[2][4], b[8][2];
            #pragma unroll
            for (int mt = 0; mt < 2; mt++) {
                int m = wm * 32 + mt * 16;
                a[mt][0] = As[(m + g) * 36 + k0 + t];
                a[mt][1] = As[(m + 8 + g) * 36 + k0 + t];
                a[mt][2] = As[(m + g) * 36 + k0 + t + 4];
                a[mt][3] = As[(m + 8 + g) * 36 + k0 + t + 4];
            }
            #pragma unroll
            for (int nt = 0; nt < 8; nt++) {
                int n = wn * 64 + nt * 8 + g;
                b[nt][0] = Bs[(k0 + t) * 132 + n];
                b[nt][1] = Bs[(k0 + t + 4) * 132 + n];
            }
            #pragma unroll
            for (int mt = 0; mt < 2; mt++)
                #pragma unroll
                for (int nt = 0; nt < 8; nt++)
                    mma_tf32(acc[mt][nt], a[mt], b[nt]);
        }
        __syncthreads();
    }

    #pragma unroll
    for (int mt = 0; mt < 2; mt++) {
        int r0 = row0 + wm * 32 + mt * 16 + g;
        int r1 = r0 + 8;
        float p0a = gridsrc[(size_t)r0 * 258 + 256], p1a = gridsrc[(size_t)r0 * 258 + 257];
        float p0b = gridsrc[(size_t)r1 * 258 + 256], p1b = gridsrc[(size_t)r1 * 258 + 257];
        float s0 = 0.f, q0 = 0.f, s1 = 0.f, q1 = 0.f;
        #pragma unroll
        for (int nt = 0; nt < 8; nt++) {
            int col = col0 + wn * 64 + nt * 8 + t * 2;
            int jm = col & 255;
            float w00 = Wp[jm],       w01 = Wp[jm + 1];
            float w10 = Wp[256 + jm], w11 = Wp[257 + jm];
            float* c = acc[mt][nt];
            c[0] += p0a * w00 + p1a * w10;
            c[1] += p0a * w01 + p1a * w11;
            c[2] += p0b * w00 + p1b * w10;
            c[3] += p0b * w01 + p1b * w11;
            s0 += c[0] + c[1]; q0 += c[0] * c[0] + c[1] * c[1];
            s1 += c[2] + c[3]; q1 += c[2] * c[2] + c[3] * c[3];
        }
        #pragma unroll
        for (int o = 1; o <= 2; o <<= 1) {
            s0 += __shfl_xor_sync(~0u, s0, o);
            q0 += __shfl_xor_sync(~0u, q0, o);
            s1 += __shfl_xor_sync(~0u, s1, o);
            q1 += __shfl_xor_sync(~0u, q1, o);
        }
        float m0 = s0 * (1.f / 64.f), m1 = s1 * (1.f / 64.f);
        float rs0 = rsqrtf(q0 * (1.f / 64.f) - m0 * m0 + 1e-6f);
        float rs1 = rsqrtf(q1 * (1.f / 64.f) - m1 * m1 + 1e-6f);
        #pragma unroll
        for (int nt = 0; nt < 8; nt++) {
            int col = col0 + wn * 64 + nt * 8 + t * 2;
            int e = col & 63;
            float sc0 = ges[e], sc1 = ges[e + 1];
            float bb0 = geb[e], bb1 = geb[e + 1];
            float* c = acc[mt][nt];
            float2 o0 = make_float2((c[0] - m0) * rs0 * sc0 + bb0,
                                    (c[1] - m0) * rs0 * sc1 + bb1);
            float2 o1 = make_float2((c[2] - m1) * rs1 * sc0 + bb0,
                                    (c[3] - m1) * rs1 * sc1 + bb1);
            *reinterpret_cast<float2*>(C + (size_t)r0 * 512 + col) = o0;
            *reinterpret_cast<float2*>(C + (size_t)r1 * 512 + col) = o1;
        }
    }
}

// ============================================================================
// k_genc: fused grid-encoder MLP over 1M 64-wide vectors (R13 version).
// ============================================================================
#define GENC_SMEM_BYTES (25856 * 4)
__global__ __launch_bounds__(256) void k_genc(
    const float* __restrict__ pre,
    const float* __restrict__ W1, const float* __restrict__ b1,
    const float* __restrict__ W2, const float* __restrict__ b2,
    float* __restrict__ out)
{
    extern __shared__ uint32_t sm[];
    uint32_t* IN  = sm;
    uint32_t* W1s = sm + 8704;
    uint32_t* HS  = sm;
    uint32_t* W2s = sm + 17152;

    int tid = threadIdx.x;
    int lane = tid & 31;
    int g = lane >> 2, t = lane & 3;
    int wid = tid >> 5;
    int wm = wid & 3, wn = wid >> 2;
    size_t v0 = (size_t)blockIdx.x * 128;

    #pragma unroll
    for (int it = 0; it < 8; it++) {
        int f4 = tid + it * 256;
        int m = f4 >> 4, k4 = (f4 & 15) * 4;
        float4 v = *reinterpret_cast<const float4*>(pre + (v0 + m) * 64 + k4);
        *reinterpret_cast<uint4*>(&IN[m * 68 + k4]) =
            make_uint4(f2tf(v.x), f2tf(v.y), f2tf(v.z), f2tf(v.w));
    }
    #pragma unroll
    for (int it = 0; it < 8; it++) {
        int f4 = tid + it * 256;
        int k = f4 >> 5, n4 = (f4 & 31) * 4;
        float4 v = *reinterpret_cast<const float4*>(W1 + (size_t)k * 128 + n4);
        *reinterpret_cast<uint4*>(&W1s[k * 132 + n4]) =
            make_uint4(f2tf(v.x), f2tf(v.y), f2tf(v.z), f2tf(v.w));
    }
    #pragma unroll
    for (int it = 0; it < 8; it++) {
        int f4 = tid + it * 256;
        int k = f4 >> 4, n4 = (f4 & 15) * 4;
        float4 v = *reinterpret_cast<const float4*>(W2 + (size_t)k * 64 + n4);
        *reinterpret_cast<uint4*>(&W2s[k * 68 + n4]) =
            make_uint4(f2tf(v.x), f2tf(v.y), f2tf(v.z), f2tf(v.w));
    }
    __syncthreads();

    float acc1[2][8][4];
    #pragma unroll
    for (int mt = 0; mt < 2; mt++)
        #pragma unroll
        for (int nt = 0; nt < 8; nt++)
            #pragma unroll
            for (int c = 0; c < 4; c++) acc1[mt][nt][c] = 0.f;

    #pragma unroll
    for (int k8 = 0; k8 < 8; k8++) {
        int k0 = k8 * 8;
        uint32_t a[2][4], b[8][2];
        #pragma unroll
        for (int mt = 0; mt < 2; mt++) {
            int m = wm * 32 + mt * 16;
            a[mt][0] = IN[(m + g) * 68 + k0 + t];
            a[mt][1] = IN[(m + 8 + g) * 68 + k0 + t];
            a[mt][2] = IN[(m + g) * 68 + k0 + t + 4];
            a[mt][3] = IN[(m + 8 + g) * 68 + k0 + t + 4];
        }
        #pragma unroll
        for (int nt = 0; nt < 8; nt++) {
            int n = wn * 64 + nt * 8 + g;
            b[nt][0] = W1s[(k0 + t) * 132 + n];
            b[nt][1] = W1s[(k0 + t + 4) * 132 + n];
        }
        #pragma unroll
        for (int mt = 0; mt < 2; mt++)
            #pragma unroll
            for (int nt = 0; nt < 8; nt++)
                mma_tf32(acc1[mt][nt], a[mt], b[nt]);
    }
    __syncthreads();

    #pragma unroll
    for (int mt = 0; mt < 2; mt++) {
        int r0 = wm * 32 + mt * 16 + g;
        int r1 = r0 + 8;
        #pragma unroll
        for (int nt = 0; nt < 8; nt++) {
            int col = wn * 64 + nt * 8 + t * 2;
            float bb0 = b1[col], bb1 = b1[col + 1];
            float* c = acc1[mt][nt];
            HS[r0 * 132 + col]     = f2tf(fmaxf(c[0] + bb0, 0.f));
            HS[r0 * 132 + col + 1] = f2tf(fmaxf(c[1] + bb1, 0.f));
            HS[r1 * 132 + col]     = f2tf(fmaxf(c[2] + bb0, 0.f));
            HS[r1 * 132 + col + 1] = f2tf(fmaxf(c[3] + bb1, 0.f));
        }
    }
    __syncthreads();

    float acc2[2][4][4];
    #pragma unroll
    for (int mt = 0; mt < 2; mt++)
        #pragma unroll
        for (int nt = 0; nt < 4; nt++)
            #pragma unroll
            for (int c = 0; c < 4; c++) acc2[mt][nt][c] = 0.f;

    #pragma unroll
    for (int k8 = 0; k8 < 16; k8++) {
        int k0 = k8 * 8;
        uint32_t a[2][4], b[4][2];
        #pragma unroll
        for (int mt = 0; mt < 2; mt++) {
            int m = wm * 32 + mt * 16;
            a[mt][0] = HS[(m + g) * 132 + k0 + t];
            a[mt][1] = HS[(m + 8 + g) * 132 + k0 + t];
            a[mt][2] = HS[(m + g) * 132 + k0 + t + 4];
            a[mt][3] = HS[(m + 8 + g) * 132 + k0 + t + 4];
        }
        #pragma unroll
        for (int nt = 0; nt < 4; nt++) {
            int n = wn * 32 + nt * 8 + g;
            b[nt][0] = W2s[(k0 + t) * 68 + n];
            b[nt][1] = W2s[(k0 + t + 4) * 68 + n];
        }
        #pragma unroll
        for (int mt = 0; mt < 2; mt++)
            #pragma unroll
            for (int nt = 0; nt < 4; nt++)
                mma_tf32(acc2[mt][nt], a[mt], b[nt]);
    }

    #pragma unroll
    for (int mt = 0; mt < 2; mt++) {
        int r0 = wm * 32 + mt * 16 + g;
        int r1 = r0 + 8;
        #pragma unroll
        for (int nt = 0; nt < 4; nt++) {
            int col = wn * 32 + nt * 8 + t * 2;
            float bb0 = b2[col], bb1 = b2[col + 1];
            float* c = acc2[mt][nt];
            *reinterpret_cast<float2*>(out + (v0 + r0) * 64 + col) =
                make_float2(c[0] + bb0, c[1] + bb1);
            *reinterpret_cast<float2*>(out + (v0 + r1) * 64 + col) =
                make_float2(c[2] + bb0, c[3] + bb1);
        }
    }
}

// ---------------- small SGEMM: BM=64 BN=64 BK=32, 256 thr, 4x4 microtile
// EPI: 0 plain, 1 +bias, 2 +bias+relu, 3 *scale, 4 res + acc + bias
template<int EPI>
__global__ __launch_bounds__(256) void k_small(
    const float* __restrict__ A, const float* __restrict__ Bm, float* __restrict__ C,
    int M, int Nc, int K,
    const float* __restrict__ bias, const float* __restrict__ res, float scale)
{
    const int BM = 64, BN = 64, BK = 32;
    __shared__ float As[BK][BM + 4];
    __shared__ float Bs[BK][BN];
    int tid = threadIdx.x;
    int tx = tid & 15, ty = tid >> 4;
    int row0 = blockIdx.y * BM;
    int col0 = blockIdx.x * BN;

    float acc[4][4];
    #pragma unroll
    for (int i = 0; i < 4; i++)
        #pragma unroll
        for (int j = 0; j < 4; j++) acc[i][j] = 0.f;

    for (int k0 = 0; k0 < K; k0 += BK) {
        #pragma unroll
        for (int it = 0; it < 2; ++it) {
            int f = tid + it * 256;
            int r = f >> 3, c = (f & 7) * 4;
            float4 v = *reinterpret_cast<const float4*>(A + (size_t)(row0 + r) * K + k0 + c);
            As[c + 0][r] = v.x; As[c + 1][r] = v.y;
            As[c + 2][r] = v.z; As[c + 3][r] = v.w;
        }
        #pragma unroll
        for (int it = 0; it < 2; ++it) {
            int f = tid + it * 256;
            int br = f >> 4, bc = (f & 15) * 4;
            *reinterpret_cast<float4*>(&Bs[br][bc]) =
                *reinterpret_cast<const float4*>(Bm + (size_t)(k0 + br) * Nc + col0 + bc);
        }
        __syncthreads();
        #pragma unroll
        for (int k = 0; k < BK; k++) {
            float4 b4 = *reinterpret_cast<const float4*>(&Bs[k][tx * 4]);
            float a0 = As[k][ty];
            float a1 = As[k][ty + 16];
            float a2 = As[k][ty + 32];
            float a3 = As[k][ty + 48];
            acc[0][0] = fmaf(a0, b4.x, acc[0][0]); acc[0][1] = fmaf(a0, b4.y, acc[0][1]);
            acc[0][2] = fmaf(a0, b4.z, acc[0][2]); acc[0][3] = fmaf(a0, b4.w, acc[0][3]);
            acc[1][0] = fmaf(a1, b4.x, acc[1][0]); acc[1][1] = fmaf(a1, b4.y, acc[1][1]);
            acc[1][2] = fmaf(a1, b4.z, acc[1][2]); acc[1][3] = fmaf(a1, b4.w, acc[1][3]);
            acc[2][0] = fmaf(a2, b4.x, acc[2][0]); acc[2][1] = fmaf(a2, b4.y, acc[2][1]);
            acc[2][2] = fmaf(a2, b4.z, acc[2][2]); acc[2][3] = fmaf(a2, b4.w, acc[2][3]);
            acc[3][0] = fmaf(a3, b4.x, acc[3][0]); acc[3][1] = fmaf(a3, b4.y, acc[3][1]);
            acc[3][2] = fmaf(a3, b4.z, acc[3][2]); acc[3][3] = fmaf(a3, b4.w, acc[3][3]);
        }
        __syncthreads();
    }

    int n = col0 + tx * 4;
    #pragma unroll
    for (int i = 0; i < 4; i++) {
        int m = row0 + ty + i * 16;
        float4 r;
        r.x = acc[i][0]; r.y = acc[i][1]; r.z = acc[i][2]; r.w = acc[i][3];
        if (EPI == 1) {
            float4 bv = *reinterpret_cast<const float4*>(bias + n);
            r.x += bv.x; r.y += bv.y; r.z += bv.z; r.w += bv.w;
        } else if (EPI == 2) {
            float4 bv = *reinterpret_cast<const float4*>(bias + n);
            r.x = fmaxf(r.x + bv.x, 0.f); r.y = fmaxf(r.y + bv.y, 0.f);
            r.z = fmaxf(r.z + bv.z, 0.f); r.w = fmaxf(r.w + bv.w, 0.f);
        } else if (EPI == 3) {
            r.x *= scale; r.y *= scale; r.z *= scale; r.w *= scale;
        } else if (EPI == 4) {
            float4 bv = *reinterpret_cast<const float4*>(bias + n);
            float4 rv = *reinterpret_cast<const float4*>(res + (size_t)m * Nc + n);
            r.x += bv.x + rv.x; r.y += bv.y + rv.y;
            r.z += bv.z + rv.z; r.w += bv.w + rv.w;
        }
        *reinterpret_cast<float4*>(C + (size_t)m * Nc + n) = r;
    }
}

// ---------------- attention pass 1: logits + softmax over slots (no atomics)
__global__ __launch_bounds__(256) void k_attn1(
    const float* __restrict__ q,
    const float* __restrict__ kv,
    float* __restrict__ attn)
{
    int bh = blockIdx.y;
    int b = bh >> 2, h = bh & 3;
    int kk = blockIdx.x * 256 + threadIdx.x;
    int tid = threadIdx.x;

    __shared__ float qs[16][64];
    {
        int row = tid >> 4, col = (tid & 15) * 4;
        float4 v = *reinterpret_cast<const float4*>(
            q + (size_t)(b * 16 + row) * 256 + h * 64 + col);
        *reinterpret_cast<float4*>(&qs[row][col]) = v;
    }
    __syncthreads();

    const float* kp = kv + (size_t)(b * 4096 + kk) * 512 + h * 64;
    float acc[16];
    #pragma unroll
    for (int s = 0; s < 16; s++) acc[s] = 0.f;
    #pragma unroll
    for (int ec = 0; ec < 16; ec++) {
        float4 k4 = *reinterpret_cast<const float4*>(kp + ec * 4);
        #pragma unroll
        for (int s = 0; s < 16; s++) {
            float4 q4 = *reinterpret_cast<const float4*>(&qs[s][ec * 4]);
            acc[s] = fmaf(k4.x, q4.x, acc[s]);
            acc[s] = fmaf(k4.y, q4.y, acc[s]);
            acc[s] = fmaf(k4.z, q4.z, acc[s]);
            acc[s] = fmaf(k4.w, q4.w, acc[s]);
        }
    }
    float mx = acc[0];
    #pragma unroll
    for (int s = 1; s < 16; s++) mx = fmaxf(mx, acc[s]);
    float tot = 0.f;
    #pragma unroll
    for (int s = 0; s < 16; s++) { acc[s] = expf(acc[s] - mx); tot += acc[s]; }
    float inv = 1.f / tot;
    float* ap = attn + ((size_t)bh * 4096 + kk) * 16;
    #pragma unroll
    for (int s4 = 0; s4 < 4; s4++) {
        float4 o;
        o.x = acc[s4 * 4 + 0] * inv;
        o.y = acc[s4 * 4 + 1] * inv;
        o.z = acc[s4 * 4 + 2] * inv;
        o.w = acc[s4 * 4 + 3] * inv;
        *reinterpret_cast<float4*>(ap + s4 * 4) = o;
    }
}

// ---------------- attention pass 2: one block per (b,h) owns full k range.
// Computes rowsums internally; writes upd directly (no atomics, no zero-init).
__global__ __launch_bounds__(512) void k_attn2(
    const float* __restrict__ attn,
    const float* __restrict__ kv,
    float* __restrict__ upd)
{
    int bh = blockIdx.x;
    int b = bh >> 2, h = bh & 3;
    int tid = threadIdx.x;
    int e = tid & 63, kg = tid >> 6;   // 8 key-groups

    __shared__ float red[8][16][64];   // 32KB
    __shared__ float srs[8][16];

    float acc[16], rsum[16];
    #pragma unroll
    for (int s = 0; s < 16; s++) { acc[s] = 0.f; rsum[s] = 0.f; }

    const float* abase = attn + (size_t)bh * 4096 * 16;
    const float* vbase = kv + (size_t)b * 4096 * 512 + 256 + h * 64 + e;
    #pragma unroll 4
    for (int j = 0; j < 512; j++) {
        int kk = j * 8 + kg;
        const float* ap = abase + (size_t)kk * 16;
        float vv = vbase[(size_t)kk * 512];
        float4 a0 = *reinterpret_cast<const float4*>(ap + 0);
        float4 a1 = *reinterpret_cast<const float4*>(ap + 4);
        float4 a2 = *reinterpret_cast<const float4*>(ap + 8);
        float4 a3 = *reinterpret_cast<const float4*>(ap + 12);
        acc[0]  = fmaf(a0.x, vv, acc[0]);  rsum[0]  += a0.x;
        acc[1]  = fmaf(a0.y, vv, acc[1]);  rsum[1]  += a0.y;
        acc[2]  = fmaf(a0.z, vv, acc[2]);  rsum[2]  += a0.z;
        acc[3]  = fmaf(a0.w, vv, acc[3]);  rsum[3]  += a0.w;
        acc[4]  = fmaf(a1.x, vv, acc[4]);  rsum[4]  += a1.x;
        acc[5]  = fmaf(a1.y, vv, acc[5]);  rsum[5]  += a1.y;
        acc[6]  = fmaf(a1.z, vv, acc[6]);  rsum[6]  += a1.z;
        acc[7]  = fmaf(a1.w, vv, acc[7]);  rsum[7]  += a1.w;
        acc[8]  = fmaf(a2.x, vv, acc[8]);  rsum[8]  += a2.x;
        acc[9]  = fmaf(a2.y, vv, acc[9]);  rsum[9]  += a2.y;
        acc[10] = fmaf(a2.z, vv, acc[10]); rsum[10] += a2.z;
        acc[11] = fmaf(a2.w, vv, acc[11]); rsum[11] += a2.w;
        acc[12] = fmaf(a3.x, vv, acc[12]); rsum[12] += a3.x;
        acc[13] = fmaf(a3.y, vv, acc[13]); rsum[13] += a3.y;
        acc[14] = fmaf(a3.z, vv, acc[14]); rsum[14] += a3.z;
        acc[15] = fmaf(a3.w, vv, acc[15]); rsum[15] += a3.w;
    }
    #pragma unroll
    for (int s = 0; s < 16; s++) red[kg][s][e] = acc[s];
    if (e == 0) {
        #pragma unroll
        for (int s = 0; s < 16; s++) srs[kg][s] = rsum[s];
    }
    __syncthreads();
    if (kg == 0) {
        #pragma unroll
        for (int s = 0; s < 16; s++) {
            float t = red[0][s][e] + red[1][s][e] + red[2][s][e] + red[3][s][e]
                    + red[4][s][e] + red[5][s][e] + red[6][s][e] + red[7][s][e];
            float rt = srs[0][s] + srs[1][s] + srs[2][s] + srs[3][s]
                     + srs[4][s] + srs[5][s] + srs[6][s] + srs[7][s];
            upd[(size_t)(b * 16 + s) * 256 + h * 64 + e] = t / (rt + 1e-8f);
        }
    }
}

// ---------------- GRU update (elementwise), one block per slot row
__global__ __launch_bounds__(256) void k_gru(
    const float* __restrict__ gi, const float* __restrict__ gh,
    const float* __restrict__ bhn, float* __restrict__ slots)
{
    int r = blockIdx.x, d = threadIdx.x;
    size_t gb = (size_t)r * 768 + d;
    float ir = gi[gb], iz = gi[gb + 256], inn = gi[gb + 512];
    float hr = gh[gb], hz = gh[gb + 256], hn  = gh[gb + 512];
    float rr = 1.f / (1.f + expf(-(ir + hr)));
    float zz = 1.f / (1.f + expf(-(iz + hz)));
    float nn = tanhf(inn + rr * (hn + bhn[d]));
    size_t sb = (size_t)r * 256 + d;
    slots[sb] = (1.f - zz) * nn + zz * slots[sb];
}

// ---------------- host orchestration ----------------
extern "C" void kernel_launch(void* const* d_in, const int* in_sizes, int n_in,
                              void* d_out, int out_size)
{
    (void)in_sizes; (void)n_in;
    const float* slots_in = (const float*)d_in[0];
    const float* inputs   = (const float*)d_in[1];
    const float* ln_in_s  = (const float*)d_in[2];
    const float* ln_in_b  = (const float*)d_in[3];
    const float* Wk       = (const float*)d_in[4];
    const float* Wv       = (const float*)d_in[5];
    const float* Wp       = (const float*)d_in[6];
    const float* ge_ln_s  = (const float*)d_in[7];
    const float* ge_ln_b  = (const float*)d_in[8];
    const float* ge_W1    = (const float*)d_in[9];
    const float* ge_b1    = (const float*)d_in[10];
    const float* ge_W2    = (const float*)d_in[11];
    const float* ge_b2    = (const float*)d_in[12];
    const float* lnq_s    = (const float*)d_in[13];
    const float* lnq_b    = (const float*)d_in[14];
    const float* Wq       = (const float*)d_in[15];
    const float* Wo       = (const float*)d_in[16];
    const float* gru_Wi   = (const float*)d_in[17];
    const float* gru_bi   = (const float*)d_in[18];
    const float* gru_Wh   = (const float*)d_in[19];
    const float* gru_bhn  = (const float*)d_in[20];
    const float* mlp_ln_s = (const float*)d_in[21];
    const float* mlp_ln_b = (const float*)d_in[22];
    const float* mlp_W1   = (const float*)d_in[23];
    const float* mlp_b1   = (const float*)d_in[24];
    const float* mlp_W2   = (const float*)d_in[25];
    const float* mlp_b2   = (const float*)d_in[26];

    float *x, *pre, *kvb, *wkv, *wog, *slots, *sn, *q, *attn;
    float *upd, *gi, *gh, *mlp1;
    cudaGetSymbolAddress((void**)&x,      g_x);
    cudaGetSymbolAddress((void**)&pre,    g_pre);
    cudaGetSymbolAddress((void**)&kvb,    g_kv);
    cudaGetSymbolAddress((void**)&wkv,    g_wkv);
    cudaGetSymbolAddress((void**)&wog,    g_wog);
    cudaGetSymbolAddress((void**)&slots,  g_slots);
    cudaGetSymbolAddress((void**)&sn,     g_sn);
    cudaGetSymbolAddress((void**)&q,      g_q);
    cudaGetSymbolAddress((void**)&attn,   g_attn);
    cudaGetSymbolAddress((void**)&upd,    g_upd);
    cudaGetSymbolAddress((void**)&gi,     g_gi);
    cudaGetSymbolAddress((void**)&gh,     g_gh);
    cudaGetSymbolAddress((void**)&mlp1,   g_mlp1);

    cudaFuncSetAttribute(k_genc, cudaFuncAttributeMaxDynamicSharedMemorySize,
                         GENC_SMEM_BYTES);

    // ---- setup ----
    k_copy<<<(CBS*CD + 255) / 256, 256>>>(slots_in, slots, CBS*CD);
    k_build_wkv<<<(CD*512 + 255) / 256, 256>>>(Wk, Wv, wkv);
    // Wog = Wo(256x256) @ gru_Wi(256x768)   (fold Wo into GRU input proj)
    k_small<0><<<dim3(768/64, 256/64), 256>>>(Wo, gru_Wi, wog, 256, 768, 256,
                                              nullptr, nullptr, 1.f);
    k_ln256<<<CT, 256>>>(inputs, 258, ln_in_s, ln_in_b, x);

    // pre = LN_ge( x @ [Wk|Wv] + positional )   (tf32 tensor cores)
    k_kvpre<<<dim3(4, 1024), 256>>>(x, wkv, pre, inputs, Wp, ge_ln_s, ge_ln_b);
    // kv = grid_enc MLP(pre)
    k_genc<<<CV8 / 128, 256, GENC_SMEM_BYTES>>>(pre, ge_W1, ge_b1, ge_W2, ge_b2, kvb);

    // ---- iterations ----
    for (int it = 0; it < 3; it++) {
        k_ln256<<<CBS, 256>>>(slots, 256, lnq_s, lnq_b, sn);
        k_small<3><<<dim3(256/64, CBS/64), 256>>>(sn, Wq, q, CBS, 256, 256,
                                                  nullptr, nullptr, 0.125f);
        k_attn1<<<dim3(16, CB*CH), 256>>>(q, kvb, attn);
        k_attn2<<<CB*CH, 512>>>(attn, kvb, upd);

        k_small<1><<<dim3(768/64, CBS/64), 256>>>(upd, wog, gi, CBS, 768, 256,
                                                  gru_bi, nullptr, 1.f);
        k_small<0><<<dim3(768/64, CBS/64), 256>>>(slots, gru_Wh, gh, CBS, 768, 256,
                                                  nullptr, nullptr, 1.f);
        k_gru<<<CBS, 256>>>(gi, gh, gru_bhn, slots);

        k_ln256<<<CBS, 256>>>(slots, 256, mlp_ln_s, mlp_ln_b, sn);
        k_small<2><<<dim3(1024/64, CBS/64), 256>>>(sn, mlp_W1, mlp1, CBS, 1024, 256,
                                                   mlp_b1, nullptr, 1.f);
        k_small<4><<<dim3(256/64, CBS/64), 256>>>(mlp1, mlp_W2, slots, CBS, 256, 1024,
                                                  mlp_b2, slots, 1.f);
    }

    k_copy<<<(CBS*CD + 255) / 256, 256>>>(slots, (float*)d_out, CBS*CD);
    (void)out_size;
}